// round 4
// baseline (speedup 1.0000x reference)
#include <cuda_runtime.h>

// out[b,c,h,w] = x[b,c,h,w] * (h%3 != 0) * (w%3 != 0)
//
// Unfold(k=2, stride=3, dil=2, pad=1) + fold with identical geometry reduces to
// an elementwise 0/1 coverage mask, separable in h and w.
//
// Rows with h%3==0 are all-zero in the output; their input line (exactly one
// 128B row) is never loaded (predicated @P LDG.128). Writes are mandatory.
//
// R4: 8 independent predicated loads per thread batched up front (MLP_p1=8) to
// close the DRAM-idle gap seen at MLP=4 (68% busy). Streaming stores (__stcs)
// keep the write stream from polluting L2. Chunk stride n4/8 is a whole number
// of 32x32 planes, so all 8 accesses of a thread share one (h,w) mask.

__global__ void unfoldfold_mask_kernel(const float4* __restrict__ x,
                                       float4* __restrict__ out,
                                       int q) {
    int i = blockIdx.x * blockDim.x + threadIdx.x;
    if (i >= q) return;

    int e  = i << 2;           // element index of .x within the plane stream
    int w0 = e & 31;           // W = 32 floats/row; float4 never crosses rows
    int h  = (e >> 5) & 31;    // H = 32

    float hm = (h % 3 != 0) ? 1.0f : 0.0f;
    float m0 = hm * (float)(((w0 + 0) % 3) != 0);
    float m1 = hm * (float)(((w0 + 1) % 3) != 0);
    float m2 = hm * (float)(((w0 + 2) % 3) != 0);
    float m3 = hm * (float)(((w0 + 3) % 3) != 0);

    bool ld = (h % 3 != 0);

    float4 v[8];
#pragma unroll
    for (int k = 0; k < 8; k++) v[k] = make_float4(0.f, 0.f, 0.f, 0.f);

    // Single-load bodies -> predicated LDG.128, batched back-to-back (MLP=8).
    if (ld) v[0] = __ldg(&x[i]);
    if (ld) v[1] = __ldg(&x[i + q]);
    if (ld) v[2] = __ldg(&x[i + 2 * q]);
    if (ld) v[3] = __ldg(&x[i + 3 * q]);
    if (ld) v[4] = __ldg(&x[i + 4 * q]);
    if (ld) v[5] = __ldg(&x[i + 5 * q]);
    if (ld) v[6] = __ldg(&x[i + 6 * q]);
    if (ld) v[7] = __ldg(&x[i + 7 * q]);

#pragma unroll
    for (int k = 0; k < 8; k++) {
        v[k].x *= m0; v[k].y *= m1; v[k].z *= m2; v[k].w *= m3;
    }

#pragma unroll
    for (int k = 0; k < 8; k++) {
        __stcs(&out[i + k * q], v[k]);   // evict-first streaming store
    }
}

extern "C" void kernel_launch(void* const* d_in, const int* in_sizes, int n_in,
                              void* d_out, int out_size) {
    const float4* x = (const float4*)d_in[0];
    float4* out     = (float4*)d_out;

    int n  = in_sizes[0];      // 64*512*32*32 = 33,554,432
    int n4 = n >> 2;           // 8,388,608 float4s
    int q  = n4 >> 3;          // 1,048,576 float4s per chunk (4096 planes)

    const int threads = 256;
    int blocks = (q + threads - 1) / threads;   // 4096 blocks
    unfoldfold_mask_kernel<<<blocks, threads>>>(x, out, q);
}

// round 5
// speedup vs baseline: 1.0401x; 1.0401x over previous
#include <cuda_runtime.h>

// out[b,c,h,w] = x[b,c,h,w] * (h%3 != 0) * (w%3 != 0)
//
// Unfold(k=2, stride=3, dil=2, pad=1) + fold with identical geometry reduces to
// an elementwise 0/1 coverage mask, separable in h and w. Rows with h%3==0 are
// all-zero in the output; their input lines are never read (predicated load).
//
// R5: 256-bit global accesses (ld.global.nc.v8.f32 / st.global.v8.f32,
// Blackwell LDG.E.256 / STG.E.256) to halve memory-op count and improve DRAM
// burst efficiency. MLP=4 (proven best in R3), plain stores, exact grid.
// One float8 = 8 floats = a quarter of a 32-float row -> never crosses a row;
// chunk stride q is a whole number of 32x32 planes, so all 4 accesses of a
// thread share one (h, w) mask.

__device__ __forceinline__ void ldg256_pred(float v[8], const float* p, int pred) {
    asm volatile(
        "{\n\t"
        ".reg .pred p0;\n\t"
        "setp.ne.s32 p0, %9, 0;\n\t"
        "@p0 ld.global.nc.v8.f32 {%0,%1,%2,%3,%4,%5,%6,%7}, [%8];\n\t"
        "}"
        : "+f"(v[0]), "+f"(v[1]), "+f"(v[2]), "+f"(v[3]),
          "+f"(v[4]), "+f"(v[5]), "+f"(v[6]), "+f"(v[7])
        : "l"(p), "r"(pred));
}

__device__ __forceinline__ void stg256(float* p, const float v[8]) {
    asm volatile(
        "st.global.v8.f32 [%0], {%1,%2,%3,%4,%5,%6,%7,%8};"
        :: "l"(p),
           "f"(v[0]), "f"(v[1]), "f"(v[2]), "f"(v[3]),
           "f"(v[4]), "f"(v[5]), "f"(v[6]), "f"(v[7])
        : "memory");
}

__global__ void __launch_bounds__(256)
unfoldfold_mask_kernel(const float* __restrict__ x,
                       float* __restrict__ out,
                       int q8) {                 // q8 = float8s per chunk
    int i = blockIdx.x * blockDim.x + threadIdx.x;   // grid covers q8 exactly

    int e  = i << 3;            // element index of lane 0 of this float8
    int w0 = e & 31;            // 0, 8, 16, or 24
    int h  = (e >> 5) & 31;     // H = 32

    int  ld = (h % 3 != 0);
    float hm = ld ? 1.0f : 0.0f;

    float m[8];
#pragma unroll
    for (int j = 0; j < 8; j++)
        m[j] = hm * (float)(((w0 + j) % 3) != 0);

    const float* base = x + (size_t)e;
    float*       obase = out + (size_t)e;
    size_t cs = (size_t)q8 << 3;   // chunk stride in floats (whole planes)

    float v0[8] = {0,0,0,0,0,0,0,0};
    float v1[8] = {0,0,0,0,0,0,0,0};
    float v2[8] = {0,0,0,0,0,0,0,0};
    float v3[8] = {0,0,0,0,0,0,0,0};

    // 4 independent predicated 256-bit loads, batched (MLP_p1 = 4)
    ldg256_pred(v0, base,          ld);
    ldg256_pred(v1, base + cs,     ld);
    ldg256_pred(v2, base + 2 * cs, ld);
    ldg256_pred(v3, base + 3 * cs, ld);

#pragma unroll
    for (int j = 0; j < 8; j++) {
        v0[j] *= m[j]; v1[j] *= m[j]; v2[j] *= m[j]; v3[j] *= m[j];
    }

    stg256(obase,          v0);
    stg256(obase + cs,     v1);
    stg256(obase + 2 * cs, v2);
    stg256(obase + 3 * cs, v3);
}

extern "C" void kernel_launch(void* const* d_in, const int* in_sizes, int n_in,
                              void* d_out, int out_size) {
    const float* x = (const float*)d_in[0];
    float* out     = (float*)d_out;

    int n  = in_sizes[0];      // 64*512*32*32 = 33,554,432 floats
    int n8 = n >> 3;           // 4,194,304 float8s
    int q8 = n8 >> 2;          // 1,048,576 float8s per chunk (8192 planes)

    const int threads = 256;
    int blocks = q8 / threads; // 4096 blocks, exact cover
    unfoldfold_mask_kernel<<<blocks, threads>>>(x, out, q8);
}

// round 6
// speedup vs baseline: 1.0446x; 1.0043x over previous
#include <cuda_runtime.h>

// out[b,c,h,w] = x[b,c,h,w] * (h%3 != 0) * (w%3 != 0)
//
// Unfold(k=2, stride=3, dil=2, pad=1) + fold with identical geometry reduces to
// an elementwise 0/1 coverage mask, separable in h and w. Rows with h%3==0 are
// all-zero in the output; their input lines (one 128B row each) are never read
// (predicated @P LDG.128). Writes are mandatory (d_out is poisoned).
// Mandatory traffic: 88 MB read + 134 MB write = 222 MB.
//
// R6 = R3 winner (float4, MLP_p1=4, single-load if-bodies -> predicated LDG)
// with 128-thread blocks: grid 16384 for minimal wave-tail quantization
// (grid 4096 in R4/R5 wasted ~half a wave; grid 8192 in R3 was near-perfect).

__global__ void __launch_bounds__(128)
unfoldfold_mask_kernel(const float4* __restrict__ x,
                       float4* __restrict__ out,
                       int q) {
    int i = blockIdx.x * blockDim.x + threadIdx.x;   // exact cover, no bound chk

    int e  = i << 2;           // element index of .x within the plane stream
    int w0 = e & 31;           // W = 32 floats/row; float4 never crosses rows
    int h  = (e >> 5) & 31;    // H = 32

    float hm = (h % 3 != 0) ? 1.0f : 0.0f;
    float m0 = hm * (float)(((w0 + 0) % 3) != 0);
    float m1 = hm * (float)(((w0 + 1) % 3) != 0);
    float m2 = hm * (float)(((w0 + 2) % 3) != 0);
    float m3 = hm * (float)(((w0 + 3) % 3) != 0);

    bool ld = (h % 3 != 0);

    float4 v0 = make_float4(0.f, 0.f, 0.f, 0.f);
    float4 v1 = v0, v2 = v0, v3 = v0;

    // Single-load bodies -> predicated LDG.128, batched back-to-back (MLP=4).
    if (ld) v0 = x[i];
    if (ld) v1 = x[i + q];
    if (ld) v2 = x[i + 2 * q];
    if (ld) v3 = x[i + 3 * q];

    v0.x *= m0; v0.y *= m1; v0.z *= m2; v0.w *= m3;
    v1.x *= m0; v1.y *= m1; v1.z *= m2; v1.w *= m3;
    v2.x *= m0; v2.y *= m1; v2.z *= m2; v2.w *= m3;
    v3.x *= m0; v3.y *= m1; v3.z *= m2; v3.w *= m3;

    out[i]         = v0;
    out[i + q]     = v1;
    out[i + 2 * q] = v2;
    out[i + 3 * q] = v3;
}

extern "C" void kernel_launch(void* const* d_in, const int* in_sizes, int n_in,
                              void* d_out, int out_size) {
    const float4* x = (const float4*)d_in[0];
    float4* out     = (float4*)d_out;

    int n  = in_sizes[0];      // 64*512*32*32 = 33,554,432
    int n4 = n >> 2;           // 8,388,608 float4s
    int q  = n4 >> 2;          // 2,097,152 float4s per chunk (8192 planes)

    const int threads = 128;
    int blocks = q / threads;  // 16384 blocks, exact cover
    unfoldfold_mask_kernel<<<blocks, threads>>>(x, out, q);
}